// round 14
// baseline (speedup 1.0000x reference)
#include <cuda_runtime.h>
#include <cuda_bf16.h>

#define DD 96
#define NSEG 50
#define NT 301
#define BATCH 256
#define OUTW 4656          // 96 + 96*95/2
#define TILES_PB 8
#define GRID (BATCH * NSEG / TILES_PB)   // 1600

// ---- Youla decomposition of the 6x6 antisymmetric tridiagonal form ----
#define S1d 0.4338837391175581204757683328483
#define S2d 0.7818314824680298087084445266741
#define S3d 0.9749279121818236070181316829939
#define C1d 0.9009688679024191262361023195074
#define C2d 0.6234898018587335305250048840042
#define C3d 0.2225209339563144042889025644968
// A[i,j] = sum_k P_k[i] Q_k[j] - Q_k[i] P_k[j]
__device__ __constant__ float PA[3][3] = {
    { (float)(-(C1d/1.75)*S2d), (float)( (C1d/1.75)*S3d), (float)(-(C1d/1.75)*S1d) },
    { (float)(-(C2d/1.75)*S3d), (float)(-(C2d/1.75)*S1d), (float)( (C2d/1.75)*S2d) },
    { (float)(-(C3d/1.75)*S1d), (float)(-(C3d/1.75)*S2d), (float)(-(C3d/1.75)*S3d) },
};
__device__ __constant__ float QB[3][3] = {
    { (float)( S1d), (float)(-S3d), (float)( S2d) },
    { (float)( S2d), (float)(-S1d), (float)(-S3d) },
    { (float)( S3d), (float)( S2d), (float)( S1d) },
};

typedef unsigned long long u64;

__device__ __forceinline__ u64 pack2f(float lo, float hi) {
    u64 r; asm("mov.b64 %0, {%1, %2};" : "=l"(r) : "f"(lo), "f"(hi)); return r;
}
__device__ __forceinline__ u64 fma2(u64 a, u64 b, u64 c) {
    u64 d; asm("fma.rn.f32x2 %0, %1, %2, %3;" : "=l"(d) : "l"(a), "l"(b), "l"(c)); return d;
}
__device__ __forceinline__ u64 mul2(u64 a, u64 b) {
    u64 d; asm("mul.rn.f32x2 %0, %1, %2;" : "=l"(d) : "l"(a), "l"(b)); return d;
}
__device__ __forceinline__ float hsum2(u64 v) {
    float lo, hi;
    asm("mov.b64 {%0, %1}, %2;" : "=f"(lo), "=f"(hi) : "l"(v));
    return lo + hi;
}

// Complex-packed staging (verified R10-R13):
//  rowPQ[k][i] = {P_ki, -Q_ki}, colPQ[k][j] = {Q_kj, P_kj};
//  acc = sum_k rowPQ[k][i] *2 colPQ[k][j]; halves sum to A[i,j].
struct SBuf {
    float2 rowPQ[3][DD];
    float2 colPQ[3][DD];
};

// R11 body: one 8-row group (half-warp: rows i0..i0+3, i0 = 8g + 4*half),
// lane owns j-pair (32*jt + 2*jl, +1), tiles jt = JTF..2; jt == JTF masked.
// Row r: r=0,1 -> odd triangular base (2x STG.32); r=2,3 -> even (STG.64).
template<int JTF>
__device__ __forceinline__ void do_group(int g, int half, int jl,
                                         const SBuf* __restrict__ sb,
                                         float* __restrict__ o)
{
    const int i0 = 8 * g + 4 * half;

    u64 rp[3][4];
    #pragma unroll
    for (int k = 0; k < 3; k++) {
        const float4 fa = *(const float4*)&sb->rowPQ[k][i0];
        const float4 fb = *(const float4*)&sb->rowPQ[k][i0 + 2];
        rp[k][0] = pack2f(fa.x, fa.y);
        rp[k][1] = pack2f(fa.z, fa.w);
        rp[k][2] = pack2f(fb.x, fb.y);
        rp[k][3] = pack2f(fb.z, fb.w);
    }

    float* rb[4];
    #pragma unroll
    for (int r = 0; r < 4; r++) {
        const int i = i0 + r;
        rb[r] = o + DD + i * 95 - ((i * (i - 1)) >> 1) - i - 1 + 2 * jl;
    }

    #pragma unroll
    for (int jt = JTF; jt < 3; jt++) {
        const int j0 = 32 * jt + 2 * jl;

        u64 cj0[3], cj1[3];
        #pragma unroll
        for (int k = 0; k < 3; k++) {
            const float4 c = *(const float4*)&sb->colPQ[k][j0];
            cj0[k] = pack2f(c.x, c.y);
            cj1[k] = pack2f(c.z, c.w);
        }

        u64 a0[4], a1[4];
        #pragma unroll
        for (int r = 0; r < 4; r++) {
            a0[r] = mul2(rp[0][r], cj0[0]);
            a0[r] = fma2(rp[1][r], cj0[1], a0[r]);
            a0[r] = fma2(rp[2][r], cj0[2], a0[r]);
            a1[r] = mul2(rp[0][r], cj1[0]);
            a1[r] = fma2(rp[1][r], cj1[1], a1[r]);
            a1[r] = fma2(rp[2][r], cj1[2], a1[r]);
        }

        const int off = 32 * jt;
        if (jt == JTF) {
            #pragma unroll
            for (int r = 0; r < 4; r++) {
                const int i = i0 + r;
                if (r < 2) {
                    if (j0     > i) rb[r][off]     = hsum2(a0[r]);
                    if (j0 + 1 > i) rb[r][off + 1] = hsum2(a1[r]);
                } else {
                    if (j0 > i) {
                        const float2 v = make_float2(hsum2(a0[r]), hsum2(a1[r]));
                        *(float2*)&rb[r][off] = v;
                    } else if (j0 == i) {
                        rb[r][off + 1] = hsum2(a1[r]);
                    }
                }
            }
        } else {
            #pragma unroll
            for (int r = 0; r < 4; r++) {
                if (r < 2) {
                    rb[r][off]     = hsum2(a0[r]);
                    rb[r][off + 1] = hsum2(a1[r]);
                } else {
                    const float2 v = make_float2(hsum2(a0[r]), hsum2(a1[r]));
                    *(float2*)&rb[r][off] = v;
                }
            }
        }
    }
}

__device__ __forceinline__ void compute_seg(int warp, int half, int jl,
                                            const SBuf* __restrict__ sb,
                                            float* __restrict__ o)
{
    if (warp < 4) {
        do_group<0>(warp, half, jl, sb, o);
    } else {
        do_group<1>(warp, half, jl, sb, o);
        do_group<2>(warp + 4, half, jl, sb, o);
    }
}

__global__ __launch_bounds__(256)
void logsig_kernel(const float* __restrict__ inp, float* __restrict__ out)
{
    __shared__ __align__(16) SBuf sb[TILES_PB];   // 36.9 KB: one slab per segment

    const int tid  = threadIdx.x;
    const int warp = tid >> 5;
    const int lane = tid & 31;
    const int half = lane >> 4;
    const int jl   = lane & 15;

    const int bs0 = blockIdx.x * TILES_PB;

    // ---- single stage phase: 192 stagers handle 4 segments each ----
    if (tid < 2 * DD) {
        const int seg = tid / DD;        // 0 or 1
        const int d   = tid - seg * DD;

        // issue all 28 loads first (max MLP), then stage
        float pf[4][7];
        #pragma unroll
        for (int h = 0; h < 4; h++) {
            const int bs = bs0 + seg + 2 * h;
            const int b = bs / NSEG, s = bs - b * NSEG;
            const float* __restrict__ p = inp + ((size_t)b * NT + 6 * s) * DD + d;
            #pragma unroll
            for (int t = 0; t < 7; t++) pf[h][t] = p[t * DD];
        }

        #pragma unroll
        for (int h = 0; h < 4; h++) {
            const int sg = seg + 2 * h;
            SBuf* sd = &sb[sg];
            float* os = out + (size_t)(bs0 + sg) * OUTW;
            const float p0 = pf[h][0];
            const float y1 = pf[h][1] - p0, y2 = pf[h][2] - p0, y3 = pf[h][3] - p0;
            const float y4 = pf[h][4] - p0, y5 = pf[h][5] - p0, y6 = pf[h][6] - p0;
            os[d] = y6;  // level-1 term
            #pragma unroll
            for (int k = 0; k < 3; k++) {
                float Pk = fmaf(PA[k][0], y2, fmaf(PA[k][1], y4, PA[k][2] * y6));
                float Qk = fmaf(QB[k][0], y1, fmaf(QB[k][1], y3, QB[k][2] * y5));
                sd->rowPQ[k][d] = make_float2(Pk, -Qk);
                sd->colPQ[k][d] = make_float2(Qk,  Pk);
            }
        }
    }
    __syncthreads();   // the only barrier in the block

    // ---- compute + store all 8 segments back-to-back ----
    #pragma unroll
    for (int sg = 0; sg < TILES_PB; sg++)
        compute_seg(warp, half, jl, &sb[sg], out + (size_t)(bs0 + sg) * OUTW);
}

extern "C" void kernel_launch(void* const* d_in, const int* in_sizes, int n_in,
                              void* d_out, int out_size)
{
    const float* inp = (const float*)d_in[0];
    float* out = (float*)d_out;
    logsig_kernel<<<GRID, 256>>>(inp, out);
}

// round 15
// speedup vs baseline: 1.0628x; 1.0628x over previous
#include <cuda_runtime.h>
#include <cuda_bf16.h>

#define DD 96
#define NSEG 50
#define NT 301
#define BATCH 256
#define OUTW 4656          // 96 + 96*95/2
#define TILES_PB 16
#define QUADS (TILES_PB / 4)
#define GRID (BATCH * NSEG / TILES_PB)   // 800

// ---- Youla decomposition of the 6x6 antisymmetric tridiagonal form ----
#define S1d 0.4338837391175581204757683328483
#define S2d 0.7818314824680298087084445266741
#define S3d 0.9749279121818236070181316829939
#define C1d 0.9009688679024191262361023195074
#define C2d 0.6234898018587335305250048840042
#define C3d 0.2225209339563144042889025644968
// A[i,j] = sum_k P_k[i] Q_k[j] - Q_k[i] P_k[j]
__device__ __constant__ float PA[3][3] = {
    { (float)(-(C1d/1.75)*S2d), (float)( (C1d/1.75)*S3d), (float)(-(C1d/1.75)*S1d) },
    { (float)(-(C2d/1.75)*S3d), (float)(-(C2d/1.75)*S1d), (float)( (C2d/1.75)*S2d) },
    { (float)(-(C3d/1.75)*S1d), (float)(-(C3d/1.75)*S2d), (float)(-(C3d/1.75)*S3d) },
};
__device__ __constant__ float QB[3][3] = {
    { (float)( S1d), (float)(-S3d), (float)( S2d) },
    { (float)( S2d), (float)(-S1d), (float)(-S3d) },
    { (float)( S3d), (float)( S2d), (float)( S1d) },
};

typedef unsigned long long u64;

__device__ __forceinline__ u64 pack2f(float lo, float hi) {
    u64 r; asm("mov.b64 %0, {%1, %2};" : "=l"(r) : "f"(lo), "f"(hi)); return r;
}
__device__ __forceinline__ u64 fma2(u64 a, u64 b, u64 c) {
    u64 d; asm("fma.rn.f32x2 %0, %1, %2, %3;" : "=l"(d) : "l"(a), "l"(b), "l"(c)); return d;
}
__device__ __forceinline__ u64 mul2(u64 a, u64 b) {
    u64 d; asm("mul.rn.f32x2 %0, %1, %2;" : "=l"(d) : "l"(a), "l"(b)); return d;
}
__device__ __forceinline__ float hsum2(u64 v) {
    float lo, hi;
    asm("mov.b64 {%0, %1}, %2;" : "=f"(lo), "=f"(hi) : "l"(v));
    return lo + hi;
}

// Complex-packed staging (verified R10-R13):
//  rowPQ[k][i] = {P_ki, -Q_ki}, colPQ[k][j] = {Q_kj, P_kj};
//  acc = sum_k rowPQ[k][i] *2 colPQ[k][j]; halves sum to A[i,j].
struct SBuf {
    float2 rowPQ[3][DD];
    float2 colPQ[3][DD];
};

// R11/R13 body: one 8-row group (half-warp: rows i0..i0+3, i0 = 8g + 4*half),
// lane owns j-pair (32*jt + 2*jl, +1), tiles jt = JTF..2; jt == JTF masked.
// Row r: r=0,1 -> odd triangular base (2x STG.32); r=2,3 -> even (STG.64).
template<int JTF>
__device__ __forceinline__ void do_group(int g, int half, int jl,
                                         const SBuf* __restrict__ sb,
                                         float* __restrict__ o)
{
    const int i0 = 8 * g + 4 * half;

    u64 rp[3][4];
    #pragma unroll
    for (int k = 0; k < 3; k++) {
        const float4 fa = *(const float4*)&sb->rowPQ[k][i0];
        const float4 fb = *(const float4*)&sb->rowPQ[k][i0 + 2];
        rp[k][0] = pack2f(fa.x, fa.y);
        rp[k][1] = pack2f(fa.z, fa.w);
        rp[k][2] = pack2f(fb.x, fb.y);
        rp[k][3] = pack2f(fb.z, fb.w);
    }

    float* rb[4];
    #pragma unroll
    for (int r = 0; r < 4; r++) {
        const int i = i0 + r;
        rb[r] = o + DD + i * 95 - ((i * (i - 1)) >> 1) - i - 1 + 2 * jl;
    }

    #pragma unroll
    for (int jt = JTF; jt < 3; jt++) {
        const int j0 = 32 * jt + 2 * jl;

        u64 cj0[3], cj1[3];
        #pragma unroll
        for (int k = 0; k < 3; k++) {
            const float4 c = *(const float4*)&sb->colPQ[k][j0];
            cj0[k] = pack2f(c.x, c.y);
            cj1[k] = pack2f(c.z, c.w);
        }

        u64 a0[4], a1[4];
        #pragma unroll
        for (int r = 0; r < 4; r++) {
            a0[r] = mul2(rp[0][r], cj0[0]);
            a0[r] = fma2(rp[1][r], cj0[1], a0[r]);
            a0[r] = fma2(rp[2][r], cj0[2], a0[r]);
            a1[r] = mul2(rp[0][r], cj1[0]);
            a1[r] = fma2(rp[1][r], cj1[1], a1[r]);
            a1[r] = fma2(rp[2][r], cj1[2], a1[r]);
        }

        const int off = 32 * jt;
        if (jt == JTF) {
            #pragma unroll
            for (int r = 0; r < 4; r++) {
                const int i = i0 + r;
                if (r < 2) {
                    if (j0     > i) rb[r][off]     = hsum2(a0[r]);
                    if (j0 + 1 > i) rb[r][off + 1] = hsum2(a1[r]);
                } else {
                    if (j0 > i) {
                        const float2 v = make_float2(hsum2(a0[r]), hsum2(a1[r]));
                        *(float2*)&rb[r][off] = v;
                    } else if (j0 == i) {
                        rb[r][off + 1] = hsum2(a1[r]);
                    }
                }
            }
        } else {
            #pragma unroll
            for (int r = 0; r < 4; r++) {
                if (r < 2) {
                    rb[r][off]     = hsum2(a0[r]);
                    rb[r][off + 1] = hsum2(a1[r]);
                } else {
                    const float2 v = make_float2(hsum2(a0[r]), hsum2(a1[r]));
                    *(float2*)&rb[r][off] = v;
                }
            }
        }
    }
}

__device__ __forceinline__ void compute_seg(int warp, int half, int jl,
                                            const SBuf* __restrict__ sb,
                                            float* __restrict__ o)
{
    if (warp < 4) {
        do_group<0>(warp, half, jl, sb, o);
    } else {
        do_group<1>(warp, half, jl, sb, o);
        do_group<2>(warp + 4, half, jl, sb, o);
    }
}

__global__ __launch_bounds__(256)
void logsig_kernel(const float* __restrict__ inp, float* __restrict__ out)
{
    __shared__ __align__(16) SBuf sb[2][4];   // [quad parity][segment in quad]

    const int tid  = threadIdx.x;
    const int warp = tid >> 5;
    const int lane = tid & 31;
    const int half = lane >> 4;
    const int jl   = lane & 15;

    const int bs0 = blockIdx.x * TILES_PB;

    // staging role: tid < 192 handles (seg = tid/96 and seg+2, d = tid%96)
    const int seg = tid / DD;           // 0,1 for stagers
    const int d   = tid - seg * DD;

    // prefetch quad 0: each stager holds two segments' inputs
    float pf[2][7];
    if (tid < 2 * DD) {
        #pragma unroll
        for (int h = 0; h < 2; h++) {
            const int bs = bs0 + seg + 2 * h;
            const int b = bs / NSEG, s = bs - b * NSEG;
            const float* __restrict__ p = inp + ((size_t)b * NT + 6 * s) * DD + d;
            #pragma unroll
            for (int t = 0; t < 7; t++) pf[h][t] = p[t * DD];
        }
    }

    for (int qd = 0; qd < QUADS; qd++) {
        const int bsA = bs0 + 4 * qd;
        float* __restrict__ oA = out + (size_t)bsA * OUTW;

        // stage all 4 segments of the quad (192 threads, 2 segments each)
        if (tid < 2 * DD) {
            #pragma unroll
            for (int h = 0; h < 2; h++) {
                const int sg = seg + 2 * h;
                SBuf* sd = &sb[qd & 1][sg];
                float* os = oA + (size_t)sg * OUTW;
                const float p0 = pf[h][0];
                const float y1 = pf[h][1] - p0, y2 = pf[h][2] - p0, y3 = pf[h][3] - p0;
                const float y4 = pf[h][4] - p0, y5 = pf[h][5] - p0, y6 = pf[h][6] - p0;
                os[d] = y6;  // level-1 term
                #pragma unroll
                for (int k = 0; k < 3; k++) {
                    float Pk = fmaf(PA[k][0], y2, fmaf(PA[k][1], y4, PA[k][2] * y6));
                    float Qk = fmaf(QB[k][0], y1, fmaf(QB[k][1], y3, QB[k][2] * y5));
                    sd->rowPQ[k][d] = make_float2(Pk, -Qk);
                    sd->colPQ[k][d] = make_float2(Qk,  Pk);
                }
            }
        }
        __syncthreads();

        // prefetch next quad (latency hidden behind this quad's compute)
        if (qd + 1 < QUADS && tid < 2 * DD) {
            #pragma unroll
            for (int h = 0; h < 2; h++) {
                const int bs2 = bs0 + 4 * (qd + 1) + seg + 2 * h;
                const int b2 = bs2 / NSEG, s2 = bs2 - b2 * NSEG;
                const float* __restrict__ p2 = inp + ((size_t)b2 * NT + 6 * s2) * DD + d;
                #pragma unroll
                for (int t = 0; t < 7; t++) pf[h][t] = p2[t * DD];
            }
        }

        // compute + store all 4 segments (4 independent store streams per warp)
        #pragma unroll
        for (int sg = 0; sg < 4; sg++)
            compute_seg(warp, half, jl, &sb[qd & 1][sg], oA + (size_t)sg * OUTW);

        // one barrier per quad suffices: compute(qd) reads buf (qd&1); the next
        // write of that buf is stage(qd+2), and barrier(qd+1) separates every
        // thread's compute(qd) from every thread's stage(qd+2).
    }
}

extern "C" void kernel_launch(void* const* d_in, const int* in_sizes, int n_in,
                              void* d_out, int out_size)
{
    const float* inp = (const float*)d_in[0];
    float* out = (float*)d_out;
    logsig_kernel<<<GRID, 256>>>(inp, out);
}

// round 16
// speedup vs baseline: 1.2148x; 1.1430x over previous
#include <cuda_runtime.h>
#include <cuda_bf16.h>

#define DD 96
#define NSEG 50
#define NT 301
#define BATCH 256
#define OUTW 4656          // 96 + 96*95/2
#define TILES_PB 8
#define QUADS (TILES_PB / 4)
#define GRID (BATCH * NSEG / TILES_PB)   // 1600

// ---- Youla decomposition of the 6x6 antisymmetric tridiagonal form ----
#define S1d 0.4338837391175581204757683328483
#define S2d 0.7818314824680298087084445266741
#define S3d 0.9749279121818236070181316829939
#define C1d 0.9009688679024191262361023195074
#define C2d 0.6234898018587335305250048840042
#define C3d 0.2225209339563144042889025644968
// A[i,j] = sum_k P_k[i] Q_k[j] - Q_k[i] P_k[j]
__device__ __constant__ float PA[3][3] = {
    { (float)(-(C1d/1.75)*S2d), (float)( (C1d/1.75)*S3d), (float)(-(C1d/1.75)*S1d) },
    { (float)(-(C2d/1.75)*S3d), (float)(-(C2d/1.75)*S1d), (float)( (C2d/1.75)*S2d) },
    { (float)(-(C3d/1.75)*S1d), (float)(-(C3d/1.75)*S2d), (float)(-(C3d/1.75)*S3d) },
};
__device__ __constant__ float QB[3][3] = {
    { (float)( S1d), (float)(-S3d), (float)( S2d) },
    { (float)( S2d), (float)(-S1d), (float)(-S3d) },
    { (float)( S3d), (float)( S2d), (float)( S1d) },
};

typedef unsigned long long u64;

__device__ __forceinline__ u64 pack2f(float lo, float hi) {
    u64 r; asm("mov.b64 %0, {%1, %2};" : "=l"(r) : "f"(lo), "f"(hi)); return r;
}
__device__ __forceinline__ u64 fma2(u64 a, u64 b, u64 c) {
    u64 d; asm("fma.rn.f32x2 %0, %1, %2, %3;" : "=l"(d) : "l"(a), "l"(b), "l"(c)); return d;
}
__device__ __forceinline__ u64 mul2(u64 a, u64 b) {
    u64 d; asm("mul.rn.f32x2 %0, %1, %2;" : "=l"(d) : "l"(a), "l"(b)); return d;
}
__device__ __forceinline__ float hsum2(u64 v) {
    float lo, hi;
    asm("mov.b64 {%0, %1}, %2;" : "=f"(lo), "=f"(hi) : "l"(v));
    return lo + hi;
}
// streaming (evict-first) stores: output is write-once, never re-read
__device__ __forceinline__ void st_cs(float* p, float v) {
    asm volatile("st.global.cs.f32 [%0], %1;" :: "l"(p), "f"(v) : "memory");
}
__device__ __forceinline__ void st_cs2(float* p, float2 v) {
    asm volatile("st.global.cs.v2.f32 [%0], {%1, %2};" :: "l"(p), "f"(v.x), "f"(v.y) : "memory");
}

// Complex-packed staging (verified R10-R13):
//  rowPQ[k][i] = {P_ki, -Q_ki}, colPQ[k][j] = {Q_kj, P_kj};
//  acc = sum_k rowPQ[k][i] *2 colPQ[k][j]; halves sum to A[i,j].
struct SBuf {
    float2 rowPQ[3][DD];
    float2 colPQ[3][DD];
};

// R13 body: one 8-row group (half-warp: rows i0..i0+3, i0 = 8g + 4*half),
// lane owns j-pair (32*jt + 2*jl, +1), tiles jt = JTF..2; jt == JTF masked.
// Row r: r=0,1 -> odd triangular base (2x STG.32); r=2,3 -> even (STG.64).
template<int JTF>
__device__ __forceinline__ void do_group(int g, int half, int jl,
                                         const SBuf* __restrict__ sb,
                                         float* __restrict__ o)
{
    const int i0 = 8 * g + 4 * half;

    u64 rp[3][4];
    #pragma unroll
    for (int k = 0; k < 3; k++) {
        const float4 fa = *(const float4*)&sb->rowPQ[k][i0];
        const float4 fb = *(const float4*)&sb->rowPQ[k][i0 + 2];
        rp[k][0] = pack2f(fa.x, fa.y);
        rp[k][1] = pack2f(fa.z, fa.w);
        rp[k][2] = pack2f(fb.x, fb.y);
        rp[k][3] = pack2f(fb.z, fb.w);
    }

    float* rb[4];
    #pragma unroll
    for (int r = 0; r < 4; r++) {
        const int i = i0 + r;
        rb[r] = o + DD + i * 95 - ((i * (i - 1)) >> 1) - i - 1 + 2 * jl;
    }

    #pragma unroll
    for (int jt = JTF; jt < 3; jt++) {
        const int j0 = 32 * jt + 2 * jl;

        u64 cj0[3], cj1[3];
        #pragma unroll
        for (int k = 0; k < 3; k++) {
            const float4 c = *(const float4*)&sb->colPQ[k][j0];
            cj0[k] = pack2f(c.x, c.y);
            cj1[k] = pack2f(c.z, c.w);
        }

        u64 a0[4], a1[4];
        #pragma unroll
        for (int r = 0; r < 4; r++) {
            a0[r] = mul2(rp[0][r], cj0[0]);
            a0[r] = fma2(rp[1][r], cj0[1], a0[r]);
            a0[r] = fma2(rp[2][r], cj0[2], a0[r]);
            a1[r] = mul2(rp[0][r], cj1[0]);
            a1[r] = fma2(rp[1][r], cj1[1], a1[r]);
            a1[r] = fma2(rp[2][r], cj1[2], a1[r]);
        }

        const int off = 32 * jt;
        if (jt == JTF) {
            #pragma unroll
            for (int r = 0; r < 4; r++) {
                const int i = i0 + r;
                if (r < 2) {
                    if (j0     > i) st_cs(&rb[r][off],     hsum2(a0[r]));
                    if (j0 + 1 > i) st_cs(&rb[r][off + 1], hsum2(a1[r]));
                } else {
                    if (j0 > i) {
                        st_cs2(&rb[r][off], make_float2(hsum2(a0[r]), hsum2(a1[r])));
                    } else if (j0 == i) {
                        st_cs(&rb[r][off + 1], hsum2(a1[r]));
                    }
                }
            }
        } else {
            #pragma unroll
            for (int r = 0; r < 4; r++) {
                if (r < 2) {
                    st_cs(&rb[r][off],     hsum2(a0[r]));
                    st_cs(&rb[r][off + 1], hsum2(a1[r]));
                } else {
                    st_cs2(&rb[r][off], make_float2(hsum2(a0[r]), hsum2(a1[r])));
                }
            }
        }
    }
}

__device__ __forceinline__ void compute_seg(int warp, int half, int jl,
                                            const SBuf* __restrict__ sb,
                                            float* __restrict__ o)
{
    if (warp < 4) {
        do_group<0>(warp, half, jl, sb, o);
    } else {
        do_group<1>(warp, half, jl, sb, o);
        do_group<2>(warp + 4, half, jl, sb, o);
    }
}

__global__ __launch_bounds__(256)
void logsig_kernel(const float* __restrict__ inp, float* __restrict__ out)
{
    __shared__ __align__(16) SBuf sb[2][4];   // [quad parity][segment in quad]

    const int tid  = threadIdx.x;
    const int warp = tid >> 5;
    const int lane = tid & 31;
    const int half = lane >> 4;
    const int jl   = lane & 15;

    const int bs0 = blockIdx.x * TILES_PB;

    // staging role: tid < 192 handles (seg = tid/96 and seg+2, d = tid%96)
    const int seg = tid / DD;           // 0,1 for stagers
    const int d   = tid - seg * DD;

    // prefetch quad 0: each stager holds two segments' inputs
    float pf[2][7];
    if (tid < 2 * DD) {
        #pragma unroll
        for (int h = 0; h < 2; h++) {
            const int bs = bs0 + seg + 2 * h;
            const int b = bs / NSEG, s = bs - b * NSEG;
            const float* __restrict__ p = inp + ((size_t)b * NT + 6 * s) * DD + d;
            #pragma unroll
            for (int t = 0; t < 7; t++) pf[h][t] = p[t * DD];
        }
    }

    for (int qd = 0; qd < QUADS; qd++) {
        const int bsA = bs0 + 4 * qd;
        float* __restrict__ oA = out + (size_t)bsA * OUTW;

        // stage all 4 segments of the quad (192 threads, 2 segments each)
        if (tid < 2 * DD) {
            #pragma unroll
            for (int h = 0; h < 2; h++) {
                const int sg = seg + 2 * h;
                SBuf* sd = &sb[qd & 1][sg];
                float* os = oA + (size_t)sg * OUTW;
                const float p0 = pf[h][0];
                const float y1 = pf[h][1] - p0, y2 = pf[h][2] - p0, y3 = pf[h][3] - p0;
                const float y4 = pf[h][4] - p0, y5 = pf[h][5] - p0, y6 = pf[h][6] - p0;
                st_cs(&os[d], y6);  // level-1 term
                #pragma unroll
                for (int k = 0; k < 3; k++) {
                    float Pk = fmaf(PA[k][0], y2, fmaf(PA[k][1], y4, PA[k][2] * y6));
                    float Qk = fmaf(QB[k][0], y1, fmaf(QB[k][1], y3, QB[k][2] * y5));
                    sd->rowPQ[k][d] = make_float2(Pk, -Qk);
                    sd->colPQ[k][d] = make_float2(Qk,  Pk);
                }
            }
        }
        __syncthreads();

        // prefetch next quad (latency hidden behind this quad's compute)
        if (qd + 1 < QUADS && tid < 2 * DD) {
            #pragma unroll
            for (int h = 0; h < 2; h++) {
                const int bs2 = bs0 + 4 * (qd + 1) + seg + 2 * h;
                const int b2 = bs2 / NSEG, s2 = bs2 - b2 * NSEG;
                const float* __restrict__ p2 = inp + ((size_t)b2 * NT + 6 * s2) * DD + d;
                #pragma unroll
                for (int t = 0; t < 7; t++) pf[h][t] = p2[t * DD];
            }
        }

        // compute + store all 4 segments (4 independent store streams per warp)
        #pragma unroll
        for (int sg = 0; sg < 4; sg++)
            compute_seg(warp, half, jl, &sb[qd & 1][sg], oA + (size_t)sg * OUTW);

        // one barrier per quad suffices: compute(qd) reads buf (qd&1); the next
        // write of that buf is stage(qd+2), and barrier(qd+1) separates every
        // thread's compute(qd) from every thread's stage(qd+2).
    }
}

extern "C" void kernel_launch(void* const* d_in, const int* in_sizes, int n_in,
                              void* d_out, int out_size)
{
    const float* inp = (const float*)d_in[0];
    float* out = (float*)d_out;
    logsig_kernel<<<GRID, 256>>>(inp, out);
}

// round 17
// speedup vs baseline: 1.2337x; 1.0155x over previous
#include <cuda_runtime.h>
#include <cuda_bf16.h>

#define DD 96
#define NSEG 50
#define NT 301
#define BATCH 256
#define OUTW 4656          // 96 + 96*95/2
#define TILES_PB 4
#define GRID (BATCH * NSEG / TILES_PB)   // 3200

// ---- Youla decomposition of the 6x6 antisymmetric tridiagonal form ----
#define S1d 0.4338837391175581204757683328483
#define S2d 0.7818314824680298087084445266741
#define S3d 0.9749279121818236070181316829939
#define C1d 0.9009688679024191262361023195074
#define C2d 0.6234898018587335305250048840042
#define C3d 0.2225209339563144042889025644968
// A[i,j] = sum_k P_k[i] Q_k[j] - Q_k[i] P_k[j]
__device__ __constant__ float PA[3][3] = {
    { (float)(-(C1d/1.75)*S2d), (float)( (C1d/1.75)*S3d), (float)(-(C1d/1.75)*S1d) },
    { (float)(-(C2d/1.75)*S3d), (float)(-(C2d/1.75)*S1d), (float)( (C2d/1.75)*S2d) },
    { (float)(-(C3d/1.75)*S1d), (float)(-(C3d/1.75)*S2d), (float)(-(C3d/1.75)*S3d) },
};
__device__ __constant__ float QB[3][3] = {
    { (float)( S1d), (float)(-S3d), (float)( S2d) },
    { (float)( S2d), (float)(-S1d), (float)(-S3d) },
    { (float)( S3d), (float)( S2d), (float)( S1d) },
};

typedef unsigned long long u64;

__device__ __forceinline__ u64 pack2f(float lo, float hi) {
    u64 r; asm("mov.b64 %0, {%1, %2};" : "=l"(r) : "f"(lo), "f"(hi)); return r;
}
__device__ __forceinline__ u64 fma2(u64 a, u64 b, u64 c) {
    u64 d; asm("fma.rn.f32x2 %0, %1, %2, %3;" : "=l"(d) : "l"(a), "l"(b), "l"(c)); return d;
}
__device__ __forceinline__ u64 mul2(u64 a, u64 b) {
    u64 d; asm("mul.rn.f32x2 %0, %1, %2;" : "=l"(d) : "l"(a), "l"(b)); return d;
}
__device__ __forceinline__ float hsum2(u64 v) {
    float lo, hi;
    asm("mov.b64 {%0, %1}, %2;" : "=f"(lo), "=f"(hi) : "l"(v));
    return lo + hi;
}
// streaming (evict-first) stores: output is write-once, never re-read
__device__ __forceinline__ void st_cs(float* p, float v) {
    asm volatile("st.global.cs.f32 [%0], %1;" :: "l"(p), "f"(v) : "memory");
}
__device__ __forceinline__ void st_cs2(float* p, float2 v) {
    asm volatile("st.global.cs.v2.f32 [%0], {%1, %2};" :: "l"(p), "f"(v.x), "f"(v.y) : "memory");
}

// Complex-packed staging (verified R10-R16):
//  rowPQ[k][i] = {P_ki, -Q_ki}, colPQ[k][j] = {Q_kj, P_kj};
//  acc = sum_k rowPQ[k][i] *2 colPQ[k][j]; halves sum to A[i,j].
struct SBuf {
    float2 rowPQ[3][DD];
    float2 colPQ[3][DD];
};

// R16 body: one 8-row group (half-warp: rows i0..i0+3, i0 = 8g + 4*half),
// lane owns j-pair (32*jt + 2*jl, +1), tiles jt = JTF..2; jt == JTF masked.
// Row r: r=0,1 -> odd triangular base (2x STG.32); r=2,3 -> even (STG.64).
template<int JTF>
__device__ __forceinline__ void do_group(int g, int half, int jl,
                                         const SBuf* __restrict__ sb,
                                         float* __restrict__ o)
{
    const int i0 = 8 * g + 4 * half;

    u64 rp[3][4];
    #pragma unroll
    for (int k = 0; k < 3; k++) {
        const float4 fa = *(const float4*)&sb->rowPQ[k][i0];
        const float4 fb = *(const float4*)&sb->rowPQ[k][i0 + 2];
        rp[k][0] = pack2f(fa.x, fa.y);
        rp[k][1] = pack2f(fa.z, fa.w);
        rp[k][2] = pack2f(fb.x, fb.y);
        rp[k][3] = pack2f(fb.z, fb.w);
    }

    float* rb[4];
    #pragma unroll
    for (int r = 0; r < 4; r++) {
        const int i = i0 + r;
        rb[r] = o + DD + i * 95 - ((i * (i - 1)) >> 1) - i - 1 + 2 * jl;
    }

    #pragma unroll
    for (int jt = JTF; jt < 3; jt++) {
        const int j0 = 32 * jt + 2 * jl;

        u64 cj0[3], cj1[3];
        #pragma unroll
        for (int k = 0; k < 3; k++) {
            const float4 c = *(const float4*)&sb->colPQ[k][j0];
            cj0[k] = pack2f(c.x, c.y);
            cj1[k] = pack2f(c.z, c.w);
        }

        u64 a0[4], a1[4];
        #pragma unroll
        for (int r = 0; r < 4; r++) {
            a0[r] = mul2(rp[0][r], cj0[0]);
            a0[r] = fma2(rp[1][r], cj0[1], a0[r]);
            a0[r] = fma2(rp[2][r], cj0[2], a0[r]);
            a1[r] = mul2(rp[0][r], cj1[0]);
            a1[r] = fma2(rp[1][r], cj1[1], a1[r]);
            a1[r] = fma2(rp[2][r], cj1[2], a1[r]);
        }

        const int off = 32 * jt;
        if (jt == JTF) {
            #pragma unroll
            for (int r = 0; r < 4; r++) {
                const int i = i0 + r;
                if (r < 2) {
                    if (j0     > i) st_cs(&rb[r][off],     hsum2(a0[r]));
                    if (j0 + 1 > i) st_cs(&rb[r][off + 1], hsum2(a1[r]));
                } else {
                    if (j0 > i) {
                        st_cs2(&rb[r][off], make_float2(hsum2(a0[r]), hsum2(a1[r])));
                    } else if (j0 == i) {
                        st_cs(&rb[r][off + 1], hsum2(a1[r]));
                    }
                }
            }
        } else {
            #pragma unroll
            for (int r = 0; r < 4; r++) {
                if (r < 2) {
                    st_cs(&rb[r][off],     hsum2(a0[r]));
                    st_cs(&rb[r][off + 1], hsum2(a1[r]));
                } else {
                    st_cs2(&rb[r][off], make_float2(hsum2(a0[r]), hsum2(a1[r])));
                }
            }
        }
    }
}

__device__ __forceinline__ void compute_seg(int warp, int half, int jl,
                                            const SBuf* __restrict__ sb,
                                            float* __restrict__ o)
{
    if (warp < 4) {
        do_group<0>(warp, half, jl, sb, o);
    } else {
        do_group<1>(warp, half, jl, sb, o);
        do_group<2>(warp + 4, half, jl, sb, o);
    }
}

__global__ __launch_bounds__(256)
void logsig_kernel(const float* __restrict__ inp, float* __restrict__ out)
{
    __shared__ __align__(16) SBuf sb[4];   // 18.4 KB: one slab per segment

    const int tid  = threadIdx.x;
    const int warp = tid >> 5;
    const int lane = tid & 31;
    const int half = lane >> 4;
    const int jl   = lane & 15;

    const int bs0 = blockIdx.x * TILES_PB;

    // ---- stage phase: 192 stagers handle 2 segments each ----
    if (tid < 2 * DD) {
        const int seg = tid / DD;        // 0 or 1
        const int d   = tid - seg * DD;

        // issue all 14 loads first (max MLP), then stage
        float pf[2][7];
        #pragma unroll
        for (int h = 0; h < 2; h++) {
            const int bs = bs0 + seg + 2 * h;
            const int b = bs / NSEG, s = bs - b * NSEG;
            const float* __restrict__ p = inp + ((size_t)b * NT + 6 * s) * DD + d;
            #pragma unroll
            for (int t = 0; t < 7; t++) pf[h][t] = p[t * DD];
        }

        #pragma unroll
        for (int h = 0; h < 2; h++) {
            const int sg = seg + 2 * h;
            SBuf* sd = &sb[sg];
            float* os = out + (size_t)(bs0 + sg) * OUTW;
            const float p0 = pf[h][0];
            const float y1 = pf[h][1] - p0, y2 = pf[h][2] - p0, y3 = pf[h][3] - p0;
            const float y4 = pf[h][4] - p0, y5 = pf[h][5] - p0, y6 = pf[h][6] - p0;
            st_cs(&os[d], y6);  // level-1 term
            #pragma unroll
            for (int k = 0; k < 3; k++) {
                float Pk = fmaf(PA[k][0], y2, fmaf(PA[k][1], y4, PA[k][2] * y6));
                float Qk = fmaf(QB[k][0], y1, fmaf(QB[k][1], y3, QB[k][2] * y5));
                sd->rowPQ[k][d] = make_float2(Pk, -Qk);
                sd->colPQ[k][d] = make_float2(Qk,  Pk);
            }
        }
    }
    __syncthreads();   // the only barrier; inter-block overlap hides the stage

    // ---- compute + store all 4 segments back-to-back ----
    #pragma unroll
    for (int sg = 0; sg < TILES_PB; sg++)
        compute_seg(warp, half, jl, &sb[sg], out + (size_t)(bs0 + sg) * OUTW);
}

extern "C" void kernel_launch(void* const* d_in, const int* in_sizes, int n_in,
                              void* d_out, int out_size)
{
    const float* inp = (const float*)d_in[0];
    float* out = (float*)d_out;
    logsig_kernel<<<GRID, 256>>>(inp, out);
}